// round 7
// baseline (speedup 1.0000x reference)
#include <cuda_runtime.h>
#include <cuda_bf16.h>
#include <math.h>

#define TT 256
#define BB 32
#define EE 512
#define HH 512
#define GG 2048
#define MM (TT*BB)

// ---- device scratch (no allocations allowed) ----
__device__ float g_xg[2u*MM*GG];          // [dir][m=t*32+b][4H], biases folded (134 MB)
__device__ float g_h[2*2*BB*HH];          // [dir][parity][b][h]
__device__ unsigned g_bar;

// ---- helpers ----
__device__ __forceinline__ unsigned pack2(__nv_bfloat16 a, __nv_bfloat16 b) {
    __nv_bfloat162 t; t.x = a; t.y = b; return *reinterpret_cast<unsigned*>(&t);
}
__device__ __forceinline__ void split1(float v, __nv_bfloat16& h, __nv_bfloat16& l) {
    h = __float2bfloat16_rn(v);
    l = __float2bfloat16_rn(v - __bfloat162float(h));
}
__device__ __forceinline__ void split2(float x0, float x1, unsigned& hi, unsigned& lo) {
    __nv_bfloat16 h0, l0, h1, l1;
    split1(x0, h0, l0); split1(x1, h1, l1);
    hi = pack2(h0, h1); lo = pack2(l0, l1);
}
__device__ __forceinline__ void mma16816(float c[4],
    unsigned a0, unsigned a1, unsigned a2, unsigned a3, unsigned b0, unsigned b1) {
    asm volatile(
        "mma.sync.aligned.m16n8k16.row.col.f32.bf16.bf16.f32 "
        "{%0,%1,%2,%3},{%4,%5,%6,%7},{%8,%9},{%0,%1,%2,%3};\n"
        : "+f"(c[0]), "+f"(c[1]), "+f"(c[2]), "+f"(c[3])
        : "r"(a0), "r"(a1), "r"(a2), "r"(a3), "r"(b0), "r"(b1));
}

__global__ void init_kernel() {
    int i = blockIdx.x * blockDim.x + threadIdx.x;
    if (i == 0) g_bar = 0u;
    if (i < 2 * 2 * BB * HH) g_h[i] = 0.0f;
}

// ---------------------------------------------------------------------------
// Phase 1: g_xg[dir][m][g] = x_row(dir,m) @ Wih + bih + bhh
// BM=128 BN=128 BK=32, 256 thr, 8 warps (4m x 2n), warp tile 32x64.
// ---------------------------------------------------------------------------
#define SA 20
#define SB 132
__global__ __launch_bounds__(256) void input_proj(
    const float* __restrict__ x,
    const float* __restrict__ Wih0, const float* __restrict__ bih0, const float* __restrict__ bhh0,
    const float* __restrict__ Wih1, const float* __restrict__ bih1, const float* __restrict__ bhh1)
{
    const int dir = blockIdx.z;
    const float* __restrict__ Wih = dir ? Wih1 : Wih0;
    const float* __restrict__ bih = dir ? bih1 : bih0;
    const float* __restrict__ bhh = dir ? bhh1 : bhh0;

    __shared__ unsigned AsH[128 * SA], AsL[128 * SA];
    __shared__ unsigned BsH[16 * SB], BsL[16 * SB];

    const int tid = threadIdx.x;
    const int warp = tid >> 5, lane = tid & 31;
    const int gq = lane >> 2, tq = lane & 3;
    const int wm = warp & 3, wn = warp >> 2;
    const int m0 = blockIdx.y * 128;
    const int n0 = blockIdx.x * 128;

    float acc[2][8][4];
    #pragma unroll
    for (int a = 0; a < 2; a++)
        #pragma unroll
        for (int b = 0; b < 8; b++)
            #pragma unroll
            for (int q = 0; q < 4; q++) acc[a][b][q] = 0.0f;

    __nv_bfloat16* bH = reinterpret_cast<__nv_bfloat16*>(BsH);
    __nv_bfloat16* bL = reinterpret_cast<__nv_bfloat16*>(BsL);

    for (int k0 = 0; k0 < EE; k0 += 32) {
        #pragma unroll
        for (int i = 0; i < 8; i++) {       // A: 128 rows x 16 k-pairs (float2 loads)
            int lin = tid + i * 256;
            int row = lin >> 4, kp = lin & 15;
            int gm = m0 + row;
            int bb = gm & 31, tt = gm >> 5;
            int ts = dir ? (TT - 1 - tt) : tt;
            const float2 v = *reinterpret_cast<const float2*>(
                x + ((size_t)bb * TT + ts) * EE + k0 + kp * 2);
            unsigned hi, lo; split2(v.x, v.y, hi, lo);
            AsH[row * SA + kp] = hi; AsL[row * SA + kp] = lo;
        }
        #pragma unroll
        for (int i = 0; i < 16; i++) {      // B: 32 k x 128 n (elementwise, k-pairs)
            int lin = tid + i * 256;
            int kk = lin >> 7, n = lin & 127;
            float v = Wih[(size_t)(k0 + kk) * GG + n0 + n];
            __nv_bfloat16 h, l; split1(v, h, l);
            int idx = ((kk >> 1) * SB + n) * 2 + (kk & 1);
            bH[idx] = h; bL[idx] = l;
        }
        __syncthreads();

        #pragma unroll
        for (int kb = 0; kb < 2; kb++) {
            const int p = kb * 8 + tq;
            unsigned ah[2][4], al[2][4];
            #pragma unroll
            for (int mt = 0; mt < 2; mt++) {
                int r0 = (wm * 32 + mt * 16 + gq) * SA;
                int r1 = r0 + 8 * SA;
                ah[mt][0] = AsH[r0 + p];     ah[mt][1] = AsH[r1 + p];
                ah[mt][2] = AsH[r0 + p + 4]; ah[mt][3] = AsH[r1 + p + 4];
                al[mt][0] = AsL[r0 + p];     al[mt][1] = AsL[r1 + p];
                al[mt][2] = AsL[r0 + p + 4]; al[mt][3] = AsL[r1 + p + 4];
            }
            #pragma unroll
            for (int nt = 0; nt < 8; nt++) {
                int n = wn * 64 + nt * 8 + gq;
                unsigned bh0 = BsH[p * SB + n], bh1 = BsH[(p + 4) * SB + n];
                unsigned bl0 = BsL[p * SB + n], bl1 = BsL[(p + 4) * SB + n];
                #pragma unroll
                for (int mt = 0; mt < 2; mt++) {
                    mma16816(acc[mt][nt], ah[mt][0], ah[mt][1], ah[mt][2], ah[mt][3], bh0, bh1);
                    mma16816(acc[mt][nt], ah[mt][0], ah[mt][1], ah[mt][2], ah[mt][3], bl0, bl1);
                    mma16816(acc[mt][nt], al[mt][0], al[mt][1], al[mt][2], al[mt][3], bh0, bh1);
                }
            }
        }
        __syncthreads();
    }

    #pragma unroll
    for (int mt = 0; mt < 2; mt++) {
        #pragma unroll
        for (int nt = 0; nt < 8; nt++) {
            int row = wm * 32 + mt * 16 + gq;
            int col = wn * 64 + nt * 8 + 2 * tq;
            size_t gm = m0 + row;
            int gn = n0 + col;
            float bs0 = bih[gn] + bhh[gn];
            float bs1 = bih[gn + 1] + bhh[gn + 1];
            size_t base = (size_t)dir * MM * GG;
            g_xg[base + gm * GG + gn]           = acc[mt][nt][0] + bs0;
            g_xg[base + gm * GG + gn + 1]       = acc[mt][nt][1] + bs1;
            g_xg[base + (gm + 8) * GG + gn]     = acc[mt][nt][2] + bs0;
            g_xg[base + (gm + 8) * GG + gn + 1] = acc[mt][nt][3] + bs1;
        }
    }
}

// ---------------------------------------------------------------------------
// Persistent recurrence: 128 blocks (2 dirs x 64 hidden-slices of 8 units).
// Whh slice resident in smem (split-bf16) for all 256 steps.
// Per step: gates[32x32] = h_prev[32x512] @ Whh_slice[512x32], then LSTM cell.
// Grid-wide software barrier per step (all 128 blocks resident).
// ---------------------------------------------------------------------------
#define SW 36
#define SH 260
#define N_WHI (256 * SW)
#define N_HHI (32 * SH)
#define SMEM_U32 (2 * N_WHI + 2 * N_HHI + 32 * 33)
#define SMEM_BYTES (SMEM_U32 * 4)

__global__ __launch_bounds__(256, 1) void lstm_persist(
    const float* __restrict__ Whh0, const float* __restrict__ Whh1,
    float* __restrict__ out)
{
    extern __shared__ unsigned su[];
    unsigned* Whi = su;
    unsigned* Wlo = Whi + N_WHI;
    unsigned* Hhi = Wlo + N_WHI;
    unsigned* Hlo = Hhi + N_HHI;
    float*    gs  = reinterpret_cast<float*>(Hlo + N_HHI);

    const int tid = threadIdx.x;
    const int d  = blockIdx.x >> 6;
    const int j0 = (blockIdx.x & 63) * 8;
    const float* __restrict__ Whh = d ? Whh1 : Whh0;

    // Stage Whh slice once: local col c = gate*8 + jj -> global col gate*512 + j0 + jj
    #pragma unroll 4
    for (int i = 0; i < 32; i++) {
        int lin = tid + i * 256;
        int kp = lin >> 5, c = lin & 31;
        int gcol = (c >> 3) * HH + j0 + (c & 7);
        float v0 = Whh[(size_t)(2 * kp)     * GG + gcol];
        float v1 = Whh[(size_t)(2 * kp + 1) * GG + gcol];
        unsigned hi, lo; split2(v0, v1, hi, lo);
        Whi[kp * SW + c] = hi; Wlo[kp * SW + c] = lo;
    }

    const int warp = tid >> 5, lane = tid & 31;
    const int gq = lane >> 2, tq = lane & 3;
    const int mh = warp & 1, ng = warp >> 1;        // 2 row-halves x 4 col-groups
    const int eb = tid >> 3, ej = tid & 7;          // elementwise: (batch, hidden)
    const size_t xbase = (size_t)d * MM * GG;

    float creg = 0.0f;
    __syncthreads();

    for (int t = 0; t < TT; t++) {
        const float* hr = g_h + ((size_t)(d * 2 + (t & 1)) * BB) * HH;
        // stage h_prev -> split-bf16 smem (L1 bypass: same-launch cross-SM data)
        #pragma unroll 8
        for (int i = 0; i < 32; i++) {
            int lin = tid + i * 256;
            int row = lin >> 8, kp = lin & 255;
            float2 v = __ldcg(reinterpret_cast<const float2*>(hr + row * HH + kp * 2));
            unsigned hi, lo; split2(v.x, v.y, hi, lo);
            Hhi[row * SH + kp] = hi; Hlo[row * SH + kp] = lo;
        }
        __syncthreads();

        float acc[2][3][4];
        #pragma unroll
        for (int p = 0; p < 2; p++)
            #pragma unroll
            for (int s = 0; s < 3; s++)
                #pragma unroll
                for (int q = 0; q < 4; q++) acc[p][s][q] = 0.0f;

        const int r0 = (mh * 16 + gq) * SH;
        const int r1 = r0 + 8 * SH;
        const int wc = ng * 8 + gq;
        #pragma unroll 8
        for (int ks = 0; ks < 32; ks++) {
            int kp0 = ks * 8 + tq;
            unsigned ah0 = Hhi[r0 + kp0], ah1 = Hhi[r1 + kp0];
            unsigned ah2 = Hhi[r0 + kp0 + 4], ah3 = Hhi[r1 + kp0 + 4];
            unsigned al0 = Hlo[r0 + kp0], al1 = Hlo[r1 + kp0];
            unsigned al2 = Hlo[r0 + kp0 + 4], al3 = Hlo[r1 + kp0 + 4];
            unsigned bh0 = Whi[kp0 * SW + wc], bh1 = Whi[(kp0 + 4) * SW + wc];
            unsigned bl0 = Wlo[kp0 * SW + wc], bl1 = Wlo[(kp0 + 4) * SW + wc];
            int p = ks & 1;
            mma16816(acc[p][0], ah0, ah1, ah2, ah3, bh0, bh1);
            mma16816(acc[p][1], ah0, ah1, ah2, ah3, bl0, bl1);
            mma16816(acc[p][2], al0, al1, al2, al3, bh0, bh1);
        }
        {
            int grow = mh * 16 + gq;
            #pragma unroll
            for (int q = 0; q < 4; q++) {
                float c = acc[0][0][q] + acc[0][1][q] + acc[0][2][q]
                        + acc[1][0][q] + acc[1][1][q] + acc[1][2][q];
                int rr = grow + ((q >> 1) << 3);
                int cc = ng * 8 + 2 * tq + (q & 1);
                gs[rr * 33 + cc] = c;
            }
        }
        __syncthreads();

        // LSTM cell: thread owns (b=eb, j=ej)
        {
            size_t m = (size_t)t * 32 + eb;
            float gi = gs[eb * 33 + ej]      + g_xg[xbase + m * GG + j0 + ej];
            float gf = gs[eb * 33 + 8 + ej]  + g_xg[xbase + m * GG + 512  + j0 + ej];
            float gg = gs[eb * 33 + 16 + ej] + g_xg[xbase + m * GG + 1024 + j0 + ej];
            float go = gs[eb * 33 + 24 + ej] + g_xg[xbase + m * GG + 1536 + j0 + ej];
            float is = 1.0f / (1.0f + expf(-gi));
            float fs = 1.0f / (1.0f + expf(-gf));
            float os = 1.0f / (1.0f + expf(-go));
            creg = fs * creg + is * tanhf(gg);
            float hv = os * tanhf(creg);
            g_h[((size_t)(d * 2 + ((t + 1) & 1)) * BB + eb) * HH + j0 + ej] = hv;
            out[((size_t)eb * TT + t) * 1024 + d * HH + j0 + ej] = hv;
        }
        __threadfence();
        __syncthreads();
        if (tid == 0) {
            atomicAdd(&g_bar, 1u);
            unsigned target = 128u * (unsigned)(t + 1);
            while (*((volatile unsigned*)&g_bar) < target) { }
        }
        __syncthreads();
        __threadfence();
    }
}

extern "C" void kernel_launch(void* const* d_in, const int* in_sizes, int n_in,
                              void* d_out, int out_size) {
    const float* x       = (const float*)d_in[0];
    const float* fwd_Wih = (const float*)d_in[1];
    const float* fwd_bih = (const float*)d_in[2];
    const float* fwd_Whh = (const float*)d_in[3];
    const float* fwd_bhh = (const float*)d_in[4];
    const float* bwd_Wih = (const float*)d_in[5];
    const float* bwd_bih = (const float*)d_in[6];
    const float* bwd_Whh = (const float*)d_in[7];
    const float* bwd_bhh = (const float*)d_in[8];
    float* out = (float*)d_out;

    init_kernel<<<256, 256>>>();
    dim3 g1(16, 64, 2);
    input_proj<<<g1, 256>>>(x, fwd_Wih, fwd_bih, fwd_bhh, bwd_Wih, bwd_bih, bwd_bhh);
    cudaFuncSetAttribute(lstm_persist, cudaFuncAttributeMaxDynamicSharedMemorySize, SMEM_BYTES);
    lstm_persist<<<128, 256, SMEM_BYTES>>>(fwd_Whh, bwd_Whh, out);
}

// round 8
// speedup vs baseline: 1.2105x; 1.2105x over previous
#include <cuda_runtime.h>
#include <cuda_bf16.h>
#include <math.h>

#define TT 256
#define BB 32
#define EE 512
#define HH 512
#define GG 2048
#define MM (TT*BB)

// ---- device scratch (no allocations allowed) ----
__device__ float g_xg[2u*MM*GG];            // [dir][m=t*32+b][4H], biases folded
__device__ uint2 g_hs[2*2*BB*256];          // [dir][parity][b][kp]: pre-split h (hi-pair, lo-pair)
__device__ unsigned g_bar;

// ---- helpers ----
__device__ __forceinline__ unsigned pack2(__nv_bfloat16 a, __nv_bfloat16 b) {
    __nv_bfloat162 t; t.x = a; t.y = b; return *reinterpret_cast<unsigned*>(&t);
}
__device__ __forceinline__ void split1(float v, __nv_bfloat16& h, __nv_bfloat16& l) {
    h = __float2bfloat16_rn(v);
    l = __float2bfloat16_rn(v - __bfloat162float(h));
}
__device__ __forceinline__ void split2(float x0, float x1, unsigned& hi, unsigned& lo) {
    __nv_bfloat16 h0, l0, h1, l1;
    split1(x0, h0, l0); split1(x1, h1, l1);
    hi = pack2(h0, h1); lo = pack2(l0, l1);
}
__device__ __forceinline__ void mma16816(float c[4],
    unsigned a0, unsigned a1, unsigned a2, unsigned a3, unsigned b0, unsigned b1) {
    asm volatile(
        "mma.sync.aligned.m16n8k16.row.col.f32.bf16.bf16.f32 "
        "{%0,%1,%2,%3},{%4,%5,%6,%7},{%8,%9},{%0,%1,%2,%3};\n"
        : "+f"(c[0]), "+f"(c[1]), "+f"(c[2]), "+f"(c[3])
        : "r"(a0), "r"(a1), "r"(a2), "r"(a3), "r"(b0), "r"(b1));
}

__global__ void init_kernel() {
    int i = blockIdx.x * blockDim.x + threadIdx.x;
    if (i == 0) g_bar = 0u;
    if (i < 2 * 2 * BB * 256) g_hs[i] = make_uint2(0u, 0u);
}

// ---------------------------------------------------------------------------
// Phase 1: g_xg[dir][m][g] = x_row(dir,m) @ Wih + bih + bhh
// BM=128 BN=128 BK=32, 256 thr, 8 warps (4m x 2n), warp tile 32x64.
// (unchanged from the validated R6 kernel)
// ---------------------------------------------------------------------------
#define SA 20
#define SB 132
__global__ __launch_bounds__(256) void input_proj(
    const float* __restrict__ x,
    const float* __restrict__ Wih0, const float* __restrict__ bih0, const float* __restrict__ bhh0,
    const float* __restrict__ Wih1, const float* __restrict__ bih1, const float* __restrict__ bhh1)
{
    const int dir = blockIdx.z;
    const float* __restrict__ Wih = dir ? Wih1 : Wih0;
    const float* __restrict__ bih = dir ? bih1 : bih0;
    const float* __restrict__ bhh = dir ? bhh1 : bhh0;

    __shared__ unsigned AsH[128 * SA], AsL[128 * SA];
    __shared__ unsigned BsH[16 * SB], BsL[16 * SB];

    const int tid = threadIdx.x;
    const int warp = tid >> 5, lane = tid & 31;
    const int gq = lane >> 2, tq = lane & 3;
    const int wm = warp & 3, wn = warp >> 2;
    const int m0 = blockIdx.y * 128;
    const int n0 = blockIdx.x * 128;

    float acc[2][8][4];
    #pragma unroll
    for (int a = 0; a < 2; a++)
        #pragma unroll
        for (int b = 0; b < 8; b++)
            #pragma unroll
            for (int q = 0; q < 4; q++) acc[a][b][q] = 0.0f;

    __nv_bfloat16* bH = reinterpret_cast<__nv_bfloat16*>(BsH);
    __nv_bfloat16* bL = reinterpret_cast<__nv_bfloat16*>(BsL);

    for (int k0 = 0; k0 < EE; k0 += 32) {
        #pragma unroll
        for (int i = 0; i < 8; i++) {
            int lin = tid + i * 256;
            int row = lin >> 4, kp = lin & 15;
            int gm = m0 + row;
            int bb = gm & 31, tt = gm >> 5;
            int ts = dir ? (TT - 1 - tt) : tt;
            const float2 v = *reinterpret_cast<const float2*>(
                x + ((size_t)bb * TT + ts) * EE + k0 + kp * 2);
            unsigned hi, lo; split2(v.x, v.y, hi, lo);
            AsH[row * SA + kp] = hi; AsL[row * SA + kp] = lo;
        }
        #pragma unroll
        for (int i = 0; i < 16; i++) {
            int lin = tid + i * 256;
            int kk = lin >> 7, n = lin & 127;
            float v = Wih[(size_t)(k0 + kk) * GG + n0 + n];
            __nv_bfloat16 h, l; split1(v, h, l);
            int idx = ((kk >> 1) * SB + n) * 2 + (kk & 1);
            bH[idx] = h; bL[idx] = l;
        }
        __syncthreads();

        #pragma unroll
        for (int kb = 0; kb < 2; kb++) {
            const int p = kb * 8 + tq;
            unsigned ah[2][4], al[2][4];
            #pragma unroll
            for (int mt = 0; mt < 2; mt++) {
                int r0 = (wm * 32 + mt * 16 + gq) * SA;
                int r1 = r0 + 8 * SA;
                ah[mt][0] = AsH[r0 + p];     ah[mt][1] = AsH[r1 + p];
                ah[mt][2] = AsH[r0 + p + 4]; ah[mt][3] = AsH[r1 + p + 4];
                al[mt][0] = AsL[r0 + p];     al[mt][1] = AsL[r1 + p];
                al[mt][2] = AsL[r0 + p + 4]; al[mt][3] = AsL[r1 + p + 4];
            }
            #pragma unroll
            for (int nt = 0; nt < 8; nt++) {
                int n = wn * 64 + nt * 8 + gq;
                unsigned bh0 = BsH[p * SB + n], bh1 = BsH[(p + 4) * SB + n];
                unsigned bl0 = BsL[p * SB + n], bl1 = BsL[(p + 4) * SB + n];
                #pragma unroll
                for (int mt = 0; mt < 2; mt++) {
                    mma16816(acc[mt][nt], ah[mt][0], ah[mt][1], ah[mt][2], ah[mt][3], bh0, bh1);
                    mma16816(acc[mt][nt], ah[mt][0], ah[mt][1], ah[mt][2], ah[mt][3], bl0, bl1);
                    mma16816(acc[mt][nt], al[mt][0], al[mt][1], al[mt][2], al[mt][3], bh0, bh1);
                }
            }
        }
        __syncthreads();
    }

    #pragma unroll
    for (int mt = 0; mt < 2; mt++) {
        #pragma unroll
        for (int nt = 0; nt < 8; nt++) {
            int row = wm * 32 + mt * 16 + gq;
            int col = wn * 64 + nt * 8 + 2 * tq;
            size_t gm = m0 + row;
            int gn = n0 + col;
            float bs0 = bih[gn] + bhh[gn];
            float bs1 = bih[gn + 1] + bhh[gn + 1];
            size_t base = (size_t)dir * MM * GG;
            g_xg[base + gm * GG + gn]           = acc[mt][nt][0] + bs0;
            g_xg[base + gm * GG + gn + 1]       = acc[mt][nt][1] + bs1;
            g_xg[base + (gm + 8) * GG + gn]     = acc[mt][nt][2] + bs0;
            g_xg[base + (gm + 8) * GG + gn + 1] = acc[mt][nt][3] + bs1;
        }
    }
}

// ---------------------------------------------------------------------------
// Persistent recurrence v2: 128 blocks x 512 threads (16 warps).
// K split across two warp-groups (warps 0-7: K[0:256), warps 8-15: K[256:512)),
// partial gate tiles summed in smem. h stored pre-split (uint2 hi/lo pairs).
// xg DRAM loads prefetched before the MMA phase. Acquire/release grid barrier.
// ---------------------------------------------------------------------------
#define SW 36
#define SH 260
#define N_WHI (256 * SW)
#define N_HHI (32 * SH)
#define GS_N  (32 * 33)
#define SMEM_U32 (2 * N_WHI + 2 * N_HHI + 2 * GS_N)
#define SMEM_BYTES (SMEM_U32 * 4)

__global__ __launch_bounds__(512, 1) void lstm_persist(
    const float* __restrict__ Whh0, const float* __restrict__ Whh1,
    float* __restrict__ out)
{
    extern __shared__ unsigned su[];
    unsigned* Whi = su;
    unsigned* Wlo = Whi + N_WHI;
    unsigned* Hhi = Wlo + N_WHI;
    unsigned* Hlo = Hhi + N_HHI;
    float*    gs  = reinterpret_cast<float*>(Hlo + N_HHI);   // [2][32*33]

    const int tid = threadIdx.x;
    const int d  = blockIdx.x >> 6;
    const int j0 = (blockIdx.x & 63) * 8;
    const float* __restrict__ Whh = d ? Whh1 : Whh0;

    // Stage Whh slice once (split-bf16): kp in [0,256), local col c = gate*8+jj
    #pragma unroll 4
    for (int i = 0; i < 16; i++) {
        int lin = tid + i * 512;
        int kp = lin >> 5, c = lin & 31;
        int gcol = (c >> 3) * HH + j0 + (c & 7);
        float v0 = Whh[(size_t)(2 * kp)     * GG + gcol];
        float v1 = Whh[(size_t)(2 * kp + 1) * GG + gcol];
        unsigned hi, lo; split2(v0, v1, hi, lo);
        Whi[kp * SW + c] = hi; Wlo[kp * SW + c] = lo;
    }

    const int warp = tid >> 5, lane = tid & 31;
    const int gq = lane >> 2, tq = lane & 3;
    const int kh = warp >> 3;                 // K half
    const int wl = warp & 7;
    const int mh = wl & 1, ng = wl >> 1;      // 2 row-halves x 4 col-groups (ng = gate)
    const int eb = tid >> 3, ej = tid & 7;    // elementwise map (threads < 256)
    const size_t xbase = (size_t)d * MM * GG;

    float creg = 0.0f;
    __syncthreads();

    for (int t = 0; t < TT; t++) {
        // ---- stage h_prev (already split) ----
        const uint4* hp = reinterpret_cast<const uint4*>(
            g_hs + ((size_t)(d * 2 + (t & 1)) * BB) * 256);
        #pragma unroll
        for (int i = 0; i < 8; i++) {
            int lin = tid + i * 512;          // uint4 index: 4096 total
            int row = lin >> 7, kq = lin & 127;
            uint4 v = __ldcg(hp + lin);       // kp=2kq: (x=hi,y=lo); kp=2kq+1: (z,w)
            *reinterpret_cast<uint2*>(&Hhi[row * SH + 2 * kq]) = make_uint2(v.x, v.z);
            *reinterpret_cast<uint2*>(&Hlo[row * SH + 2 * kq]) = make_uint2(v.y, v.w);
        }
        // ---- prefetch xg (h-independent DRAM reads; overlap with MMA) ----
        float xgi = 0.f, xgf = 0.f, xgg = 0.f, xgo = 0.f;
        if (tid < 256) {
            size_t m = (size_t)t * 32 + eb;
            const float* xp = g_xg + xbase + m * GG + j0 + ej;
            xgi = __ldcg(xp);
            xgf = __ldcg(xp + 512);
            xgg = __ldcg(xp + 1024);
            xgo = __ldcg(xp + 1536);
        }
        __syncthreads();

        // ---- gates partial: [32x32] = h[32, Khalf] @ Whh[Khalf, 32] ----
        float acc[2][3][4];
        #pragma unroll
        for (int p = 0; p < 2; p++)
            #pragma unroll
            for (int s = 0; s < 3; s++)
                #pragma unroll
                for (int q = 0; q < 4; q++) acc[p][s][q] = 0.0f;

        const int r0 = (mh * 16 + gq) * SH;
        const int r1 = r0 + 8 * SH;
        const int wc = ng * 8 + gq;
        #pragma unroll 8
        for (int ks = 0; ks < 16; ks++) {
            int kp0 = (kh * 16 + ks) * 8 + tq;
            unsigned ah0 = Hhi[r0 + kp0],     ah1 = Hhi[r1 + kp0];
            unsigned ah2 = Hhi[r0 + kp0 + 4], ah3 = Hhi[r1 + kp0 + 4];
            unsigned al0 = Hlo[r0 + kp0],     al1 = Hlo[r1 + kp0];
            unsigned al2 = Hlo[r0 + kp0 + 4], al3 = Hlo[r1 + kp0 + 4];
            unsigned bh0 = Whi[kp0 * SW + wc], bh1 = Whi[(kp0 + 4) * SW + wc];
            unsigned bl0 = Wlo[kp0 * SW + wc], bl1 = Wlo[(kp0 + 4) * SW + wc];
            int p = ks & 1;
            mma16816(acc[p][0], ah0, ah1, ah2, ah3, bh0, bh1);
            mma16816(acc[p][1], ah0, ah1, ah2, ah3, bl0, bl1);
            mma16816(acc[p][2], al0, al1, al2, al3, bh0, bh1);
        }
        {
            int grow = mh * 16 + gq;
            float* gsd = gs + kh * GS_N;
            #pragma unroll
            for (int q = 0; q < 4; q++) {
                float c = acc[0][0][q] + acc[0][1][q] + acc[0][2][q]
                        + acc[1][0][q] + acc[1][1][q] + acc[1][2][q];
                int rr = grow + ((q >> 1) << 3);
                int cc = ng * 8 + 2 * tq + (q & 1);
                gsd[rr * 33 + cc] = c;
            }
        }
        __syncthreads();

        // ---- LSTM cell (threads 0..255 own (b=eb, j=ej)) ----
        if (tid < 256) {
            float gi = gs[eb * 33 + ej]      + gs[GS_N + eb * 33 + ej]      + xgi;
            float gf = gs[eb * 33 + 8 + ej]  + gs[GS_N + eb * 33 + 8 + ej]  + xgf;
            float gg = gs[eb * 33 + 16 + ej] + gs[GS_N + eb * 33 + 16 + ej] + xgg;
            float go = gs[eb * 33 + 24 + ej] + gs[GS_N + eb * 33 + 24 + ej] + xgo;
            float is = 1.0f / (1.0f + expf(-gi));
            float fs = 1.0f / (1.0f + expf(-gf));
            float os = 1.0f / (1.0f + expf(-go));
            creg = fs * creg + is * tanhf(gg);
            float hv = os * tanhf(creg);
            out[((size_t)eb * TT + t) * 1024 + d * HH + j0 + ej] = hv;
            // pre-split h for next step (pair lanes ej even/odd)
            float hv2 = __shfl_xor_sync(0xffffffffu, hv, 1);
            if ((ej & 1) == 0) {
                __nv_bfloat16 h0, l0, h1, l1;
                split1(hv,  h0, l0);
                split1(hv2, h1, l1);
                uint2 pv; pv.x = pack2(h0, h1); pv.y = pack2(l0, l1);
                g_hs[((size_t)(d * 2 + ((t + 1) & 1)) * BB + eb) * 256 + (j0 + ej) / 2] = pv;
            }
        }

        // ---- grid barrier (skip after last step) ----
        if (t < TT - 1) {
            __threadfence();
            __syncthreads();
            if (tid == 0) {
                atomicAdd(&g_bar, 1u);
                unsigned target = 128u * (unsigned)(t + 1);
                unsigned v;
                do {
                    asm volatile("ld.acquire.gpu.global.u32 %0, [%1];"
                                 : "=r"(v) : "l"(&g_bar));
                } while (v < target);
            }
            __syncthreads();
        }
    }
}

extern "C" void kernel_launch(void* const* d_in, const int* in_sizes, int n_in,
                              void* d_out, int out_size) {
    const float* x       = (const float*)d_in[0];
    const float* fwd_Wih = (const float*)d_in[1];
    const float* fwd_bih = (const float*)d_in[2];
    const float* fwd_Whh = (const float*)d_in[3];
    const float* fwd_bhh = (const float*)d_in[4];
    const float* bwd_Wih = (const float*)d_in[5];
    const float* bwd_bih = (const float*)d_in[6];
    const float* bwd_Whh = (const float*)d_in[7];
    const float* bwd_bhh = (const float*)d_in[8];
    float* out = (float*)d_out;

    init_kernel<<<256, 256>>>();
    dim3 g1(16, 64, 2);
    input_proj<<<g1, 256>>>(x, fwd_Wih, fwd_bih, fwd_bhh, bwd_Wih, bwd_bih, bwd_bhh);
    cudaFuncSetAttribute(lstm_persist, cudaFuncAttributeMaxDynamicSharedMemorySize, SMEM_BYTES);
    lstm_persist<<<128, 512, SMEM_BYTES>>>(fwd_Whh, bwd_Whh, out);
}

// round 9
// speedup vs baseline: 1.3874x; 1.1462x over previous
#include <cuda_runtime.h>
#include <cuda_bf16.h>
#include <math.h>

#define TT 256
#define BB 32
#define EE 512
#define HH 512
#define GG 2048
#define MM (TT*BB)

// ---- device scratch (no allocations allowed) ----
__device__ float g_xg[2u*MM*GG];       // [dir][m=t*32+b][4H], biases folded
__device__ uint2 g_hs[2*2*BB*256];     // [dir][parity][b][pw]: pre-split h, k-permuted
__device__ unsigned g_bar[2];          // per-direction barrier counters

// ---- helpers ----
__device__ __forceinline__ unsigned pack2(__nv_bfloat16 a, __nv_bfloat16 b) {
    __nv_bfloat162 t; t.x = a; t.y = b; return *reinterpret_cast<unsigned*>(&t);
}
__device__ __forceinline__ void split1(float v, __nv_bfloat16& h, __nv_bfloat16& l) {
    h = __float2bfloat16_rn(v);
    l = __float2bfloat16_rn(v - __bfloat162float(h));
}
__device__ __forceinline__ void split2(float x0, float x1, unsigned& hi, unsigned& lo) {
    __nv_bfloat16 h0, l0, h1, l1;
    split1(x0, h0, l0); split1(x1, h1, l1);
    hi = pack2(h0, h1); lo = pack2(l0, l1);
}
__device__ __forceinline__ void mma16816(float c[4],
    unsigned a0, unsigned a1, unsigned a2, unsigned a3, unsigned b0, unsigned b1) {
    asm volatile(
        "mma.sync.aligned.m16n8k16.row.col.f32.bf16.bf16.f32 "
        "{%0,%1,%2,%3},{%4,%5,%6,%7},{%8,%9},{%0,%1,%2,%3};\n"
        : "+f"(c[0]), "+f"(c[1]), "+f"(c[2]), "+f"(c[3])
        : "r"(a0), "r"(a1), "r"(a2), "r"(a3), "r"(b0), "r"(b1));
}

// ---------------------------------------------------------------------------
// Phase 1: g_xg[dir][m][g] = x_row(dir,m) @ Wih + bih + bhh  (validated R6/R7)
// Block (0,0,0) additionally zeroes g_hs parity-0 and the barrier counters.
// ---------------------------------------------------------------------------
#define SA 20
#define SB 132
__global__ __launch_bounds__(256) void input_proj(
    const float* __restrict__ x,
    const float* __restrict__ Wih0, const float* __restrict__ bih0, const float* __restrict__ bhh0,
    const float* __restrict__ Wih1, const float* __restrict__ bih1, const float* __restrict__ bhh1)
{
    const int tid = threadIdx.x;
    if (blockIdx.x == 0 && blockIdx.y == 0 && blockIdx.z == 0) {
        // zero parity-0 h buffers for both directions + barrier counters
        for (int i = tid; i < 8192; i += 256) {
            g_hs[i] = make_uint2(0u, 0u);            // d=0, parity=0
            g_hs[16384 + i] = make_uint2(0u, 0u);    // d=1, parity=0
        }
        if (tid < 2) g_bar[tid] = 0u;
    }

    const int dir = blockIdx.z;
    const float* __restrict__ Wih = dir ? Wih1 : Wih0;
    const float* __restrict__ bih = dir ? bih1 : bih0;
    const float* __restrict__ bhh = dir ? bhh1 : bhh0;

    __shared__ unsigned AsH[128 * SA], AsL[128 * SA];
    __shared__ unsigned BsH[16 * SB], BsL[16 * SB];

    const int warp = tid >> 5, lane = tid & 31;
    const int gq = lane >> 2, tq = lane & 3;
    const int wm = warp & 3, wn = warp >> 2;
    const int m0 = blockIdx.y * 128;
    const int n0 = blockIdx.x * 128;

    float acc[2][8][4];
    #pragma unroll
    for (int a = 0; a < 2; a++)
        #pragma unroll
        for (int b = 0; b < 8; b++)
            #pragma unroll
            for (int q = 0; q < 4; q++) acc[a][b][q] = 0.0f;

    __nv_bfloat16* bH = reinterpret_cast<__nv_bfloat16*>(BsH);
    __nv_bfloat16* bL = reinterpret_cast<__nv_bfloat16*>(BsL);

    for (int k0 = 0; k0 < EE; k0 += 32) {
        #pragma unroll
        for (int i = 0; i < 8; i++) {
            int lin = tid + i * 256;
            int row = lin >> 4, kp = lin & 15;
            int gm = m0 + row;
            int bb = gm & 31, tt = gm >> 5;
            int ts = dir ? (TT - 1 - tt) : tt;
            const float2 v = *reinterpret_cast<const float2*>(
                x + ((size_t)bb * TT + ts) * EE + k0 + kp * 2);
            unsigned hi, lo; split2(v.x, v.y, hi, lo);
            AsH[row * SA + kp] = hi; AsL[row * SA + kp] = lo;
        }
        #pragma unroll
        for (int i = 0; i < 16; i++) {
            int lin = tid + i * 256;
            int kk = lin >> 7, n = lin & 127;
            float v = Wih[(size_t)(k0 + kk) * GG + n0 + n];
            __nv_bfloat16 h, l; split1(v, h, l);
            int idx = ((kk >> 1) * SB + n) * 2 + (kk & 1);
            bH[idx] = h; bL[idx] = l;
        }
        __syncthreads();

        #pragma unroll
        for (int kb = 0; kb < 2; kb++) {
            const int p = kb * 8 + tq;
            unsigned ah[2][4], al[2][4];
            #pragma unroll
            for (int mt = 0; mt < 2; mt++) {
                int r0 = (wm * 32 + mt * 16 + gq) * SA;
                int r1 = r0 + 8 * SA;
                ah[mt][0] = AsH[r0 + p];     ah[mt][1] = AsH[r1 + p];
                ah[mt][2] = AsH[r0 + p + 4]; ah[mt][3] = AsH[r1 + p + 4];
                al[mt][0] = AsL[r0 + p];     al[mt][1] = AsL[r1 + p];
                al[mt][2] = AsL[r0 + p + 4]; al[mt][3] = AsL[r1 + p + 4];
            }
            #pragma unroll
            for (int nt = 0; nt < 8; nt++) {
                int n = wn * 64 + nt * 8 + gq;
                unsigned bh0 = BsH[p * SB + n], bh1 = BsH[(p + 4) * SB + n];
                unsigned bl0 = BsL[p * SB + n], bl1 = BsL[(p + 4) * SB + n];
                #pragma unroll
                for (int mt = 0; mt < 2; mt++) {
                    mma16816(acc[mt][nt], ah[mt][0], ah[mt][1], ah[mt][2], ah[mt][3], bh0, bh1);
                    mma16816(acc[mt][nt], ah[mt][0], ah[mt][1], ah[mt][2], ah[mt][3], bl0, bl1);
                    mma16816(acc[mt][nt], al[mt][0], al[mt][1], al[mt][2], al[mt][3], bh0, bh1);
                }
            }
        }
        __syncthreads();
    }

    #pragma unroll
    for (int mt = 0; mt < 2; mt++) {
        #pragma unroll
        for (int nt = 0; nt < 8; nt++) {
            int row = wm * 32 + mt * 16 + gq;
            int col = wn * 64 + nt * 8 + 2 * tq;
            size_t gm = m0 + row;
            int gn = n0 + col;
            float bs0 = bih[gn] + bhh[gn];
            float bs1 = bih[gn + 1] + bhh[gn + 1];
            size_t base = (size_t)dir * MM * GG;
            g_xg[base + gm * GG + gn]           = acc[mt][nt][0] + bs0;
            g_xg[base + gm * GG + gn + 1]       = acc[mt][nt][1] + bs1;
            g_xg[base + (gm + 8) * GG + gn]     = acc[mt][nt][2] + bs0;
            g_xg[base + (gm + 8) * GG + gn + 1] = acc[mt][nt][3] + bs1;
        }
    }
}

// ---------------------------------------------------------------------------
// Persistent recurrence v3: 128 blocks x 512 threads (16 warps).
// Warp (kh,mh): kh in 0..7 = K-slice of 64, mh = batch-row half (16 rows).
// Whh fragments live in REGISTERS for all 256 steps (64 u32/lane).
// Each warp stages only its own h slice (warp-local, no block sync).
// Per k16 iter: 4x LDS.64 (A hi/lo) feed 12 MMAs (all 4 gates x 3 split terms).
// Per-direction grid barrier (64 arrivals).
// ---------------------------------------------------------------------------
#define SH2 264                       // h row stride in words (==8 mod 32: conflict-free)
#define GSN 1088                      // 32*34 per-kh gate partial
#define N_H (32 * SH2)
#define SMEM_U32 (2 * N_H + 8 * GSN)
#define SMEM_BYTES (SMEM_U32 * 4)     // 102400 B

__global__ __launch_bounds__(512, 1) void lstm_persist(
    const float* __restrict__ Whh0, const float* __restrict__ Whh1,
    float* __restrict__ out)
{
    extern __shared__ unsigned su[];
    unsigned* Hhi = su;               // [32][SH2] permuted-k words
    unsigned* Hlo = Hhi + N_H;
    float*    gs  = reinterpret_cast<float*>(Hlo + N_H);  // [8][32][34]

    const int tid  = threadIdx.x;
    const int warp = tid >> 5, lane = tid & 31;
    const int gq = lane >> 2, tq = lane & 3;
    const int kh = warp >> 1, mh = warp & 1;
    const int d  = blockIdx.x >> 6;
    const int j0 = (blockIdx.x & 63) * 8;
    const float* __restrict__ Whh = d ? Whh1 : Whh0;
    const int eb = tid >> 3, ej = tid & 7;   // cell map (threads < 256)
    const size_t xbase = (size_t)d * MM * GG;

    // ---- preload Whh fragments to registers (once) ----
    unsigned wbh[4][4][2], wbl[4][4][2];     // [k16 iter][gate][k8 half]
    #pragma unroll
    for (int i = 0; i < 4; i++)
        #pragma unroll
        for (int g = 0; g < 4; g++) {
            int gcol = g * HH + j0 + gq;
            #pragma unroll
            for (int hf = 0; hf < 2; hf++) {
                int kp = kh * 32 + i * 8 + hf * 4 + tq;
                float v0 = Whh[(size_t)(2 * kp)     * GG + gcol];
                float v1 = Whh[(size_t)(2 * kp + 1) * GG + gcol];
                split2(v0, v1, wbh[i][g][hf], wbl[i][g][hf]);
            }
        }

    float creg = 0.0f;

    for (int t = 0; t < TT; t++) {
        // ---- warp-local h staging: 16 rows x 32 kp (already split+permuted) ----
        const uint4* hp = reinterpret_cast<const uint4*>(
            g_hs + ((size_t)(d * 2 + (t & 1)) * BB) * 256);
        #pragma unroll
        for (int l = 0; l < 8; l++) {
            int idx = lane + 32 * l;             // 0..255
            int rl = idx >> 4, qq = idx & 15;
            int row = mh * 16 + rl;
            uint4 v = __ldcg(hp + row * 128 + kh * 16 + qq);
            int w = row * SH2 + kh * 32 + 2 * qq;
            *reinterpret_cast<uint2*>(&Hhi[w]) = make_uint2(v.x, v.z);
            *reinterpret_cast<uint2*>(&Hlo[w]) = make_uint2(v.y, v.w);
        }
        // ---- xg prefetch (independent DRAM reads, consumed in cell phase) ----
        float xgi = 0.f, xgf = 0.f, xgg = 0.f, xgo = 0.f;
        if (tid < 256) {
            const float* xp = g_xg + xbase + ((size_t)t * 32 + eb) * GG + j0 + ej;
            xgi = __ldcg(xp);
            xgf = __ldcg(xp + 512);
            xgg = __ldcg(xp + 1024);
            xgo = __ldcg(xp + 1536);
        }
        __syncwarp();

        // ---- MMA: gates partial [16 rows x 32 cols] over this warp's K-slice ----
        float acc[4][4];
        #pragma unroll
        for (int g = 0; g < 4; g++)
            #pragma unroll
            for (int q = 0; q < 4; q++) acc[g][q] = 0.0f;

        #pragma unroll
        for (int i = 0; i < 4; i++) {
            int wb = (mh * 16 + gq) * SH2 + (kh * 4 + i) * 8 + tq * 2;
            uint2 h0 = *reinterpret_cast<const uint2*>(&Hhi[wb]);
            uint2 h1 = *reinterpret_cast<const uint2*>(&Hhi[wb + 8 * SH2]);
            uint2 l0 = *reinterpret_cast<const uint2*>(&Hlo[wb]);
            uint2 l1 = *reinterpret_cast<const uint2*>(&Hlo[wb + 8 * SH2]);
            #pragma unroll
            for (int g = 0; g < 4; g++)
                mma16816(acc[g], h0.x, h1.x, h0.y, h1.y, wbh[i][g][0], wbh[i][g][1]);
            #pragma unroll
            for (int g = 0; g < 4; g++)
                mma16816(acc[g], h0.x, h1.x, h0.y, h1.y, wbl[i][g][0], wbl[i][g][1]);
            #pragma unroll
            for (int g = 0; g < 4; g++)
                mma16816(acc[g], l0.x, l1.x, l0.y, l1.y, wbh[i][g][0], wbh[i][g][1]);
        }
        {
            float* gp = gs + kh * GSN;
            int rrb = mh * 16 + gq;
            #pragma unroll
            for (int g = 0; g < 4; g++) {
                *reinterpret_cast<float2*>(&gp[rrb * 34 + g * 8 + 2 * tq])
                    = make_float2(acc[g][0], acc[g][1]);
                *reinterpret_cast<float2*>(&gp[(rrb + 8) * 34 + g * 8 + 2 * tq])
                    = make_float2(acc[g][2], acc[g][3]);
            }
        }
        __syncthreads();

        // ---- LSTM cell: threads 0..255 own (b=eb, j=ej); reduce 8 K-partials ----
        if (tid < 256) {
            float gi = xgi, gf = xgf, gg = xgg, go = xgo;
            #pragma unroll
            for (int k = 0; k < 8; k++) {
                int base = k * GSN + eb * 34 + ej;
                gi += gs[base];
                gf += gs[base + 8];
                gg += gs[base + 16];
                go += gs[base + 24];
            }
            float is = 1.0f / (1.0f + expf(-gi));
            float fs = 1.0f / (1.0f + expf(-gf));
            float os = 1.0f / (1.0f + expf(-go));
            creg = fs * creg + is * tanhf(gg);
            float hv = os * tanhf(creg);
            out[((size_t)eb * TT + t) * 1024 + d * HH + j0 + ej] = hv;
            // pre-split + k-permute h for next step (lane-pair via shfl)
            float hv2 = __shfl_xor_sync(0xffffffffu, hv, 1);
            if ((ej & 1) == 0) {
                __nv_bfloat16 h0, l0, h1, l1;
                split1(hv,  h0, l0);
                split1(hv2, h1, l1);
                uint2 pv; pv.x = pack2(h0, h1); pv.y = pack2(l0, l1);
                int kp = (j0 + ej) >> 1;
                int pw = ((kp >> 3) << 3) | ((kp & 3) << 1) | ((kp >> 2) & 1);
                g_hs[((size_t)(d * 2 + ((t + 1) & 1)) * BB + eb) * 256 + pw] = pv;
            }
        }

        // ---- per-direction grid barrier (skip after last step) ----
        if (t < TT - 1) {
            __syncthreads();
            if (tid == 0) {
                __threadfence();
                atomicAdd(&g_bar[d], 1u);
                unsigned tgt = 64u * (unsigned)(t + 1);
                unsigned v;
                do {
                    asm volatile("ld.acquire.gpu.global.u32 %0, [%1];"
                                 : "=r"(v) : "l"(&g_bar[d]));
                } while (v < tgt);
            }
            __syncthreads();
        }
    }
}

extern "C" void kernel_launch(void* const* d_in, const int* in_sizes, int n_in,
                              void* d_out, int out_size) {
    const float* x       = (const float*)d_in[0];
    const float* fwd_Wih = (const float*)d_in[1];
    const float* fwd_bih = (const float*)d_in[2];
    const float* fwd_Whh = (const float*)d_in[3];
    const float* fwd_bhh = (const float*)d_in[4];
    const float* bwd_Wih = (const float*)d_in[5];
    const float* bwd_bih = (const float*)d_in[6];
    const float* bwd_Whh = (const float*)d_in[7];
    const float* bwd_bhh = (const float*)d_in[8];
    float* out = (float*)d_out;

    dim3 g1(16, 64, 2);
    input_proj<<<g1, 256>>>(x, fwd_Wih, fwd_bih, fwd_bhh, bwd_Wih, bwd_bih, bwd_bhh);
    cudaFuncSetAttribute(lstm_persist, cudaFuncAttributeMaxDynamicSharedMemorySize, SMEM_BYTES);
    lstm_persist<<<128, 512, SMEM_BYTES>>>(fwd_Whh, bwd_Whh, out);
}